// round 7
// baseline (speedup 1.0000x reference)
#include <cuda_runtime.h>
#include <cuda_bf16.h>
#include <cstdint>

#define BB 32
#define CH 1024
#define SP 1024
#define CQ 128

// ---------------- scratch ----------------
__device__ __nv_bfloat16 g_xT[(size_t)BB * SP * CH];   // [b][n][c]
__device__ __nv_bfloat16 g_Qb[(size_t)BB * SP * CQ];   // [b][n][o]
__device__ __nv_bfloat16 g_Kb[(size_t)BB * SP * CQ];   // [b][m][o]
__device__ __nv_bfloat16 g_P [(size_t)BB * CH * SP];   // attT[b][m][n] = exp(e[n][m])
__device__ float         g_scale[(size_t)BB * SP];     // gamma / rowsum[n]
__device__ __nv_bfloat16 g_Wqk[(size_t)2 * CQ * CH];   // [Wq rows; Wk rows]
__device__ __nv_bfloat16 g_Wvb[(size_t)CH * CH];

// ---------------- helpers ----------------
__device__ __forceinline__ uint32_t smem_u32(const void* p) {
    uint32_t a;
    asm("{ .reg .u64 t; cvta.to.shared.u64 t, %1; cvt.u32.u64 %0, t; }" : "=r"(a) : "l"(p));
    return a;
}
#define CP16(d, s) \
    asm volatile("cp.async.cg.shared.global [%0], [%1], 16;" :: "r"(d), "l"(s) : "memory")
#define CP_COMMIT() asm volatile("cp.async.commit_group;" ::: "memory")
#define CP_WAIT0()  asm volatile("cp.async.wait_group 0;" ::: "memory")
#define CP_WAIT1()  asm volatile("cp.async.wait_group 1;" ::: "memory")

__device__ __forceinline__ void ldm_x4(uint32_t (&r)[4], uint32_t a) {
    asm volatile("ldmatrix.sync.aligned.m8n8.x4.shared.b16 {%0,%1,%2,%3}, [%4];"
        : "=r"(r[0]), "=r"(r[1]), "=r"(r[2]), "=r"(r[3]) : "r"(a));
}
__device__ __forceinline__ void mma16816(float (&c)[4], const uint32_t (&a)[4],
                                         uint32_t b0, uint32_t b1) {
    asm volatile(
        "mma.sync.aligned.m16n8k16.row.col.f32.bf16.bf16.f32 "
        "{%0,%1,%2,%3}, {%4,%5,%6,%7}, {%8,%9}, {%0,%1,%2,%3};"
        : "+f"(c[0]), "+f"(c[1]), "+f"(c[2]), "+f"(c[3])
        : "r"(a[0]), "r"(a[1]), "r"(a[2]), "r"(a[3]), "r"(b0), "r"(b1));
}
__device__ __forceinline__ float fast_exp(float x) {
    float t = fmaf(x, 12102203.0f, 1064866805.0f);
    return __int_as_float((int)t);
}

// ---------------- kernel: convert weights; build [Wq;Wk] concat ----------------
__global__ void k_cvtall(const float* __restrict__ Wq, const float* __restrict__ Wk,
                         const float* __restrict__ Wv) {
    const int QK = CQ * CH;
    int i = (blockIdx.x * 256 + threadIdx.x) * 4;
    const float* s; __nv_bfloat16* d; int so, dofs;
    if (i < QK)            { s = Wq; d = g_Wqk; so = i;          dofs = i; }
    else if (i < 2 * QK)   { s = Wk; d = g_Wqk; so = i - QK;     dofs = i; }
    else                   { s = Wv; d = g_Wvb; so = i - 2 * QK; dofs = so; }
    float4 v = *reinterpret_cast<const float4*>(s + so);
    *reinterpret_cast<__nv_bfloat162*>(d + dofs)     = __floats2bfloat162_rn(v.x, v.y);
    *reinterpret_cast<__nv_bfloat162*>(d + dofs + 2) = __floats2bfloat162_rn(v.z, v.w);
}

// ---------------- kernel: x[b][c][n] fp32 -> xT[b][n][c] bf16 (64x64 tiles) ----------------
__global__ void __launch_bounds__(256) k_transpose(const float* __restrict__ x) {
    __shared__ float ts[64][68];
    const int b = blockIdx.z, c0 = blockIdx.y * 64, n0 = blockIdx.x * 64;
    const int tid = threadIdx.x;
    {
        const int r = tid >> 4, c4 = (tid & 15) * 4;
        const float* src = x + ((size_t)b * CH + c0 + r) * SP + n0 + c4;
#pragma unroll
        for (int u = 0; u < 4; u++) {
            float4 v = *reinterpret_cast<const float4*>(src + (size_t)u * 16 * SP);
            ts[r + u * 16][c4] = v.x; ts[r + u * 16][c4 + 1] = v.y;
            ts[r + u * 16][c4 + 2] = v.z; ts[r + u * 16][c4 + 3] = v.w;
        }
    }
    __syncthreads();
    {
        const int ch = (tid & 7) * 8;
        __nv_bfloat16* dst = g_xT + ((size_t)b * SP + n0) * CH + c0 + ch;
#pragma unroll
        for (int u = 0; u < 2; u++) {
            int nn = (tid >> 3) + u * 32;
            __nv_bfloat162 h0 = __floats2bfloat162_rn(ts[ch][nn],     ts[ch + 1][nn]);
            __nv_bfloat162 h1 = __floats2bfloat162_rn(ts[ch + 2][nn], ts[ch + 3][nn]);
            __nv_bfloat162 h2 = __floats2bfloat162_rn(ts[ch + 4][nn], ts[ch + 5][nn]);
            __nv_bfloat162 h3 = __floats2bfloat162_rn(ts[ch + 6][nn], ts[ch + 7][nn]);
            uint4 o;
            o.x = *reinterpret_cast<uint32_t*>(&h0);
            o.y = *reinterpret_cast<uint32_t*>(&h1);
            o.z = *reinterpret_cast<uint32_t*>(&h2);
            o.w = *reinterpret_cast<uint32_t*>(&h3);
            *reinterpret_cast<uint4*>(dst + (size_t)nn * CH) = o;
        }
    }
}

// ---------------- GEMM core v2: 128(A) x 256(B) tile, K=1024, BK=64, 3-stage ----------------
// stage = A 128x144B (18432) + B 256x144B (36864) = 55296 B; 3 stages = 165888 B
#define ST_SZ 55296
#define GEMM2_SMEM 165888
__device__ __forceinline__ void stage384(uint32_t sdst, const __nv_bfloat16* Ag,
                                         const __nv_bfloat16* Bg, int tid) {
#pragma unroll
    for (int u = 0; u < 4; u++) {          // A: 128 rows x 8 chunks
        int idx = tid + u * 256, r = idx >> 3, c = idx & 7;
        CP16(sdst + r * 144 + c * 16, Ag + (size_t)r * CH + c * 8);
    }
#pragma unroll
    for (int u = 0; u < 8; u++) {          // B: 256 rows x 8 chunks
        int idx = tid + u * 256, r = idx >> 3, c = idx & 7;
        CP16(sdst + 18432 + r * 144 + c * 16, Bg + (size_t)r * CH + c * 8);
    }
}
// warp tile 64(A-m) x 64(B-n); 8 warps as 2(m) x 4(n)
__device__ __forceinline__ void mma_block384(uint32_t sA, uint32_t sB,
                                             float (&acc)[4][8][4], int lane, int wm, int wn) {
#pragma unroll
    for (int ks = 0; ks < 4; ks++) {
        uint32_t a[4][4];
#pragma unroll
        for (int i = 0; i < 4; i++)
            ldm_x4(a[i], sA + ((wm + i * 16 + (lane & 15)) * 72 + ks * 16 + ((lane >> 4) << 3)) * 2);
        uint32_t bf[4][4];
#pragma unroll
        for (int jp = 0; jp < 4; jp++)
            ldm_x4(bf[jp], sB + ((wn + jp * 16 + ((lane >> 4) << 3) + (lane & 7)) * 72
                                 + ks * 16 + (((lane >> 3) & 1) << 3)) * 2);
#pragma unroll
        for (int i = 0; i < 4; i++)
#pragma unroll
            for (int j = 0; j < 8; j++)
                mma16816(acc[i][j], a[i], bf[j >> 1][(j & 1) * 2], bf[j >> 1][(j & 1) * 2 + 1]);
    }
}
__device__ __forceinline__ void gemm_bigN(const __nv_bfloat16* Ag, const __nv_bfloat16* Bg,
                                          uint32_t sb, float (&acc)[4][8][4],
                                          int tid, int lane, int wm, int wn) {
    stage384(sb,         Ag,      Bg,      tid); CP_COMMIT();
    stage384(sb + ST_SZ, Ag + 64, Bg + 64, tid); CP_COMMIT();
#pragma unroll 1
    for (int kc = 0; kc < 16; kc++) {
        if (kc == 15) CP_WAIT0(); else CP_WAIT1();
        __syncthreads();   // group kc landed everywhere; mma(kc-1) done -> buf (kc+2)%3 free
        if (kc < 14) {
            stage384(sb + ((kc + 2) % 3) * ST_SZ, Ag + (kc + 2) * 64, Bg + (kc + 2) * 64, tid);
            CP_COMMIT();
        }
        uint32_t s = (kc % 3) * ST_SZ;
        mma_block384(sb + s, sb + s + 18432, acc, lane, wm, wn);
    }
}

// ---------------- kernel: fused Q+K projection ----------------
// A = xT[b][r0..r0+127][:], B = [Wq;Wk] (256 rows). cols<128 -> Q, else -> K.
__global__ void __launch_bounds__(256, 1) k_proj(const float* __restrict__ bq,
                                                 const float* __restrict__ bk) {
    extern __shared__ char sm[];
    uint32_t sb = smem_u32(sm);
    const int tid = threadIdx.x, lane = tid & 31, wid = tid >> 5;
    const int wm = (wid >> 2) * 64, wn = (wid & 3) * 64;
    const int b = blockIdx.y, r0 = blockIdx.x * 128;

    float acc[4][8][4];
#pragma unroll
    for (int i = 0; i < 4; i++)
#pragma unroll
        for (int j = 0; j < 8; j++)
#pragma unroll
            for (int k = 0; k < 4; k++) acc[i][j][k] = 0.0f;

    gemm_bigN(g_xT + ((size_t)b * SP + r0) * CH, g_Wqk, sb, acc, tid, lane, wm, wn);

    const bool isK = (wn >= 128);
    __nv_bfloat16* dst = isK ? g_Kb : g_Qb;
    const float* bias = isK ? bk : bq;
    const int coff = isK ? 128 : 0;
#pragma unroll
    for (int j = 0; j < 8; j++) {
        int col = wn + j * 8 + (lane & 3) * 2 - coff;
        float b0 = bias[col], b1 = bias[col + 1];
#pragma unroll
        for (int i = 0; i < 4; i++) {
            int rr = r0 + wm + i * 16 + (lane >> 2);
            *reinterpret_cast<__nv_bfloat162*>(&dst[((size_t)b * SP + rr) * CQ + col]) =
                __floats2bfloat162_rn(acc[i][j][0] + b0, acc[i][j][1] + b1);
            *reinterpret_cast<__nv_bfloat162*>(&dst[((size_t)b * SP + rr + 8) * CQ + col]) =
                __floats2bfloat162_rn(acc[i][j][2] + b0, acc[i][j][3] + b1);
        }
    }
}

// ---------------- kernel: energy + softmax, 64-row n-tiles (unchanged R6) ----------------
#define ELD 136
#define E_K0 17408
#define E_K1 52224
#define E_P  87040
#define E_SUM 105472
#define EN_SMEM 105984
__global__ void __launch_bounds__(256, 2) k_energy(const float* __restrict__ gm) {
    extern __shared__ char sm[];
    uint32_t sb = smem_u32(sm);
    float* s_sum = reinterpret_cast<float*>(sm + E_SUM);
    __nv_bfloat16* Ps = reinterpret_cast<__nv_bfloat16*>(sm + E_P);
    const int tid = threadIdx.x, lane = tid & 31, wid = tid >> 5;
    const int wnn = (wid >> 2) * 32, wmm = (wid & 3) * 32;
    const int b = blockIdx.y, n0 = blockIdx.x * 64;

    if (tid < 64) s_sum[tid] = 0.0f;

    const __nv_bfloat16* Qg = g_Qb + ((size_t)b * SP + n0) * CQ;
    const __nv_bfloat16* Kg = g_Kb + (size_t)b * SP * CQ;
#pragma unroll
    for (int u = 0; u < 4; u++) {
        int idx = tid + u * 256, r = idx >> 4, c = idx & 15;
        CP16(sb + r * 272 + c * 16, Qg + (size_t)r * CQ + c * 8);
    }
#pragma unroll
    for (int u = 0; u < 8; u++) {
        int idx = tid + u * 256, r = idx >> 4, c = idx & 15;
        CP16(sb + E_K0 + r * 272 + c * 16, Kg + (size_t)r * CQ + c * 8);
    }
    CP_COMMIT();
#pragma unroll
    for (int u = 0; u < 8; u++) {
        int idx = tid + u * 256, r = idx >> 4, c = idx & 15;
        CP16(sb + E_K1 + r * 272 + c * 16, Kg + (size_t)(128 + r) * CQ + c * 8);
    }
    CP_COMMIT();

#pragma unroll 1
    for (int mc = 0; mc < 8; mc++) {
        if (mc == 7) CP_WAIT0(); else CP_WAIT1();
        __syncthreads();
        const uint32_t kb = (mc & 1) ? E_K1 : E_K0;
        float acc[2][4][4];
#pragma unroll
        for (int i = 0; i < 2; i++)
#pragma unroll
            for (int j = 0; j < 4; j++)
#pragma unroll
                for (int k = 0; k < 4; k++) acc[i][j][k] = 0.0f;
#pragma unroll
        for (int ks = 0; ks < 8; ks++) {
            uint32_t a[2][4];
#pragma unroll
            for (int i = 0; i < 2; i++)
                ldm_x4(a[i], sb + ((wnn + i * 16 + (lane & 15)) * ELD
                                   + ks * 16 + ((lane >> 4) << 3)) * 2);
            uint32_t bf[2][4];
#pragma unroll
            for (int jp = 0; jp < 2; jp++)
                ldm_x4(bf[jp], sb + kb + ((wmm + jp * 16 + ((lane >> 4) << 3) + (lane & 7)) * ELD
                                          + ks * 16 + (((lane >> 3) & 1) << 3)) * 2);
#pragma unroll
            for (int i = 0; i < 2; i++)
#pragma unroll
                for (int j = 0; j < 4; j++)
                    mma16816(acc[i][j], a[i], bf[j >> 1][(j & 1) * 2], bf[j >> 1][(j & 1) * 2 + 1]);
        }
        __syncthreads();
        if (mc < 6) {
            const __nv_bfloat16* Kn = Kg + (size_t)(mc + 2) * 128 * CQ;
#pragma unroll
            for (int u = 0; u < 8; u++) {
                int idx = tid + u * 256, r = idx >> 4, c = idx & 15;
                CP16(sb + kb + r * 272 + c * 16, Kn + (size_t)r * CQ + c * 8);
            }
            CP_COMMIT();
        }
#pragma unroll
        for (int i = 0; i < 2; i++) {
            int nA = wnn + i * 16 + (lane >> 2), nB = nA + 8;
            float s0 = 0.0f, s1 = 0.0f;
#pragma unroll
            for (int j = 0; j < 4; j++) {
                int mcol = wmm + j * 8 + (lane & 3) * 2;
                float p0 = fast_exp(acc[i][j][0]), p1 = fast_exp(acc[i][j][1]);
                float p2 = fast_exp(acc[i][j][2]), p3 = fast_exp(acc[i][j][3]);
                s0 += p0 + p1; s1 += p2 + p3;
                Ps[(size_t)mcol * 72 + nA]       = __float2bfloat16(p0);
                Ps[(size_t)(mcol + 1) * 72 + nA] = __float2bfloat16(p1);
                Ps[(size_t)mcol * 72 + nB]       = __float2bfloat16(p2);
                Ps[(size_t)(mcol + 1) * 72 + nB] = __float2bfloat16(p3);
            }
            s0 += __shfl_xor_sync(0xffffffffu, s0, 1);
            s0 += __shfl_xor_sync(0xffffffffu, s0, 2);
            s1 += __shfl_xor_sync(0xffffffffu, s1, 1);
            s1 += __shfl_xor_sync(0xffffffffu, s1, 2);
            if ((lane & 3) == 0) { atomicAdd(&s_sum[nA], s0); atomicAdd(&s_sum[nB], s1); }
        }
        __syncthreads();
#pragma unroll
        for (int u = 0; u < 4; u++) {
            int idx = tid + u * 256, r = idx >> 3, c = idx & 7;
            uint4 v = *reinterpret_cast<uint4*>(sm + E_P + (r * 72 + c * 8) * 2);
            *reinterpret_cast<uint4*>(
                &g_P[((size_t)b * CH + mc * 128 + r) * SP + n0 + c * 8]) = v;
        }
    }
    __syncthreads();
    if (tid < 64)
        g_scale[(size_t)b * SP + n0 + tid] = gm[0] / s_sum[tid];
}

// ---------------- kernel: V GEMM (128m x 256n) fused with apply ----------------
__global__ void __launch_bounds__(256, 1) k_vapply(const float* __restrict__ bv,
                                                   const float* __restrict__ x,
                                                   float* __restrict__ out) {
    extern __shared__ char sm[];
    uint32_t sb = smem_u32(sm);
    const int tid = threadIdx.x, lane = tid & 31, wid = tid >> 5;
    const int wm = (wid >> 2) * 64, wn = (wid & 3) * 64;
    const int b = blockIdx.z, m0 = blockIdx.y * 128, n0 = blockIdx.x * 256;

    float acc[4][8][4];
#pragma unroll
    for (int i = 0; i < 4; i++)
#pragma unroll
        for (int j = 0; j < 8; j++)
#pragma unroll
            for (int k = 0; k < 4; k++) acc[i][j][k] = 0.0f;

    gemm_bigN(g_Wvb + (size_t)m0 * CH, g_xT + ((size_t)b * SP + n0) * CH,
              sb, acc, tid, lane, wm, wn);

#pragma unroll
    for (int i = 0; i < 4; i++) {
        int mA = m0 + wm + i * 16 + (lane >> 2), mB = mA + 8;
        float bvA = bv[mA], bvB = bv[mB];
#pragma unroll
        for (int j = 0; j < 8; j++) {
            int n = n0 + wn + j * 8 + (lane & 3) * 2;
            size_t pa = ((size_t)b * CH + mA) * SP + n;
            size_t pb = ((size_t)b * CH + mB) * SP + n;
            float2 sc = *reinterpret_cast<const float2*>(&g_scale[(size_t)b * SP + n]);
            __nv_bfloat162 PA = *reinterpret_cast<const __nv_bfloat162*>(&g_P[pa]);
            __nv_bfloat162 PB = *reinterpret_cast<const __nv_bfloat162*>(&g_P[pb]);
            float2 xa = *reinterpret_cast<const float2*>(&x[pa]);
            float2 xb = *reinterpret_cast<const float2*>(&x[pb]);
            float2 oa, ob;
            oa.x = fmaf((acc[i][j][0] + bvA) * __bfloat162float(PA.x), sc.x, xa.x);
            oa.y = fmaf((acc[i][j][1] + bvA) * __bfloat162float(PA.y), sc.y, xa.y);
            ob.x = fmaf((acc[i][j][2] + bvB) * __bfloat162float(PB.x), sc.x, xb.x);
            ob.y = fmaf((acc[i][j][3] + bvB) * __bfloat162float(PB.y), sc.y, xb.y);
            *reinterpret_cast<float2*>(&out[pa]) = oa;
            *reinterpret_cast<float2*>(&out[pb]) = ob;
        }
    }
}

// ---------------- launcher ----------------
extern "C" void kernel_launch(void* const* d_in, const int* in_sizes, int n_in,
                              void* d_out, int out_size) {
    const float* x  = (const float*)d_in[0];
    const float* Wq = (const float*)d_in[1];
    const float* bq = (const float*)d_in[2];
    const float* Wk = (const float*)d_in[3];
    const float* bk = (const float*)d_in[4];
    const float* Wv = (const float*)d_in[5];
    const float* bv = (const float*)d_in[6];
    const float* gm = (const float*)d_in[7];
    float* out = (float*)d_out;

    cudaFuncSetAttribute(k_proj,   cudaFuncAttributeMaxDynamicSharedMemorySize, GEMM2_SMEM);
    cudaFuncSetAttribute(k_vapply, cudaFuncAttributeMaxDynamicSharedMemorySize, GEMM2_SMEM);
    cudaFuncSetAttribute(k_energy, cudaFuncAttributeMaxDynamicSharedMemorySize, EN_SMEM);

    k_cvtall<<<(2 * CQ * CH + CH * CH) / 1024, 256>>>(Wq, Wk, Wv);
    k_transpose<<<dim3(SP / 64, CH / 64, BB), 256>>>(x);
    k_proj<<<dim3(SP / 128, BB), 256, GEMM2_SMEM>>>(bq, bk);
    k_energy<<<dim3(SP / 64, BB), 256, EN_SMEM>>>(gm);
    k_vapply<<<dim3(SP / 256, CH / 128, BB), 256, GEMM2_SMEM>>>(bv, x, out);
}

// round 8
// speedup vs baseline: 1.0498x; 1.0498x over previous
#include <cuda_runtime.h>
#include <cuda_bf16.h>
#include <cstdint>

#define BB 32
#define CH 1024
#define SP 1024
#define CQ 128

// ---------------- scratch ----------------
__device__ __nv_bfloat16 g_xT[(size_t)BB * SP * CH];   // [b][n][c]
__device__ __nv_bfloat16 g_Qb[(size_t)BB * SP * CQ];   // [b][n][o]
__device__ __nv_bfloat16 g_Kb[(size_t)BB * SP * CQ];   // [b][m][o]
__device__ __nv_bfloat16 g_P [(size_t)BB * CH * SP];   // attT[b][m][n] = exp(e[n][m])
__device__ float         g_scale[(size_t)BB * SP];     // gamma / rowsum[n]
__device__ __nv_bfloat16 g_Wqb[CQ * CH];
__device__ __nv_bfloat16 g_Wkb[CQ * CH];
__device__ __nv_bfloat16 g_Wvb[(size_t)CH * CH];

// ---------------- helpers ----------------
__device__ __forceinline__ uint32_t smem_u32(const void* p) {
    uint32_t a;
    asm("{ .reg .u64 t; cvta.to.shared.u64 t, %1; cvt.u32.u64 %0, t; }" : "=r"(a) : "l"(p));
    return a;
}
#define CP16(d, s) \
    asm volatile("cp.async.cg.shared.global [%0], [%1], 16;" :: "r"(d), "l"(s) : "memory")
#define CP_COMMIT() asm volatile("cp.async.commit_group;" ::: "memory")
#define CP_WAIT0()  asm volatile("cp.async.wait_group 0;" ::: "memory")
#define CP_WAIT1()  asm volatile("cp.async.wait_group 1;" ::: "memory")
#define CP_WAIT2()  asm volatile("cp.async.wait_group 2;" ::: "memory")

__device__ __forceinline__ void ldm_x4(uint32_t (&r)[4], uint32_t a) {
    asm volatile("ldmatrix.sync.aligned.m8n8.x4.shared.b16 {%0,%1,%2,%3}, [%4];"
        : "=r"(r[0]), "=r"(r[1]), "=r"(r[2]), "=r"(r[3]) : "r"(a));
}
__device__ __forceinline__ void mma16816(float (&c)[4], const uint32_t (&a)[4],
                                         uint32_t b0, uint32_t b1) {
    asm volatile(
        "mma.sync.aligned.m16n8k16.row.col.f32.bf16.bf16.f32 "
        "{%0,%1,%2,%3}, {%4,%5,%6,%7}, {%8,%9}, {%0,%1,%2,%3};"
        : "+f"(c[0]), "+f"(c[1]), "+f"(c[2]), "+f"(c[3])
        : "r"(a[0]), "r"(a[1]), "r"(a[2]), "r"(a[3]), "r"(b0), "r"(b1));
}
__device__ __forceinline__ float fast_exp(float x) {
    float t = fmaf(x, 12102203.0f, 1064866805.0f);
    return __int_as_float((int)t);
}

// ---------------- kernel: convert all weights fp32->bf16 ----------------
__global__ void k_cvtall(const float* __restrict__ Wq, const float* __restrict__ Wk,
                         const float* __restrict__ Wv) {
    int i = (blockIdx.x * 256 + threadIdx.x) * 4;
    const float* s; __nv_bfloat16* d; int off;
    if (i < CQ * CH)            { s = Wq; d = g_Wqb; off = i; }
    else if (i < 2 * CQ * CH)   { s = Wk; d = g_Wkb; off = i - CQ * CH; }
    else                        { s = Wv; d = g_Wvb; off = i - 2 * CQ * CH; }
    float4 v = *reinterpret_cast<const float4*>(s + off);
    *reinterpret_cast<__nv_bfloat162*>(d + off)     = __floats2bfloat162_rn(v.x, v.y);
    *reinterpret_cast<__nv_bfloat162*>(d + off + 2) = __floats2bfloat162_rn(v.z, v.w);
}

// ---------------- kernel: x[b][c][n] fp32 -> xT[b][n][c] bf16 (64x64 tiles) ----------------
__global__ void __launch_bounds__(256) k_transpose(const float* __restrict__ x) {
    __shared__ float ts[64][68];
    const int b = blockIdx.z, c0 = blockIdx.y * 64, n0 = blockIdx.x * 64;
    const int tid = threadIdx.x;
    {
        const int r = tid >> 4, c4 = (tid & 15) * 4;
        const float* src = x + ((size_t)b * CH + c0 + r) * SP + n0 + c4;
#pragma unroll
        for (int u = 0; u < 4; u++) {
            float4 v = *reinterpret_cast<const float4*>(src + (size_t)u * 16 * SP);
            ts[r + u * 16][c4] = v.x; ts[r + u * 16][c4 + 1] = v.y;
            ts[r + u * 16][c4 + 2] = v.z; ts[r + u * 16][c4 + 3] = v.w;
        }
    }
    __syncthreads();
    {
        const int ch = (tid & 7) * 8;
        __nv_bfloat16* dst = g_xT + ((size_t)b * SP + n0) * CH + c0 + ch;
#pragma unroll
        for (int u = 0; u < 2; u++) {
            int nn = (tid >> 3) + u * 32;
            __nv_bfloat162 h0 = __floats2bfloat162_rn(ts[ch][nn],     ts[ch + 1][nn]);
            __nv_bfloat162 h1 = __floats2bfloat162_rn(ts[ch + 2][nn], ts[ch + 3][nn]);
            __nv_bfloat162 h2 = __floats2bfloat162_rn(ts[ch + 4][nn], ts[ch + 5][nn]);
            __nv_bfloat162 h3 = __floats2bfloat162_rn(ts[ch + 6][nn], ts[ch + 7][nn]);
            uint4 o;
            o.x = *reinterpret_cast<uint32_t*>(&h0);
            o.y = *reinterpret_cast<uint32_t*>(&h1);
            o.z = *reinterpret_cast<uint32_t*>(&h2);
            o.w = *reinterpret_cast<uint32_t*>(&h3);
            *reinterpret_cast<uint4*>(dst + (size_t)nn * CH) = o;
        }
    }
}

// ---------------- GEMM core v3: 128x128 tile, K=1024, BK=32, 4-stage, 1 sync/iter ----------
// row stride 80 B (conflict-free ldmatrix); stage = A 128x80 + B 128x80 = 20480 B;
// 4 stages = 81920 B -> 2 CTAs/SM.
#define ST32 20480
#define GEMM_SMEM 81920
__device__ __forceinline__ void stage32(uint32_t sdst, const __nv_bfloat16* Ag,
                                        const __nv_bfloat16* Bg, int tid) {
#pragma unroll
    for (int u = 0; u < 2; u++) {          // A: 128 rows x 4 chunks of 16B
        int idx = tid + u * 256, r = idx >> 2, c = idx & 3;
        CP16(sdst + r * 80 + c * 16, Ag + (size_t)r * CH + c * 8);
    }
#pragma unroll
    for (int u = 0; u < 2; u++) {          // B: 128 rows x 4 chunks
        int idx = tid + u * 256, r = idx >> 2, c = idx & 3;
        CP16(sdst + 10240 + r * 80 + c * 16, Bg + (size_t)r * CH + c * 8);
    }
}
__device__ __forceinline__ void mma_block32(uint32_t sA, uint32_t sB,
                                            float (&acc)[4][4][4], int lane, int wm, int wn) {
#pragma unroll
    for (int ks = 0; ks < 2; ks++) {
        uint32_t a[4][4];
#pragma unroll
        for (int i = 0; i < 4; i++)
            ldm_x4(a[i], sA + (wm + i * 16 + (lane & 15)) * 80 + ks * 32 + ((lane >> 4) << 4));
        uint32_t bf[2][4];
#pragma unroll
        for (int jp = 0; jp < 2; jp++)
            ldm_x4(bf[jp], sB + (wn + jp * 16 + ((lane >> 4) << 3) + (lane & 7)) * 80
                              + ks * 32 + (((lane >> 3) & 1) << 4));
#pragma unroll
        for (int i = 0; i < 4; i++)
#pragma unroll
            for (int j = 0; j < 4; j++)
                mma16816(acc[i][j], a[i], bf[j >> 1][(j & 1) * 2], bf[j >> 1][(j & 1) * 2 + 1]);
    }
}
__device__ __forceinline__ void gemm_1024(const __nv_bfloat16* Ag, const __nv_bfloat16* Bg,
                                          uint32_t sb, float (&acc)[4][4][4],
                                          int tid, int lane, int wm, int wn) {
    stage32(sb,            Ag,      Bg,      tid); CP_COMMIT();
    stage32(sb + ST32,     Ag + 32, Bg + 32, tid); CP_COMMIT();
    stage32(sb + 2 * ST32, Ag + 64, Bg + 64, tid); CP_COMMIT();
#pragma unroll 1
    for (int kc = 0; kc < 32; kc++) {
        if (kc >= 29) CP_WAIT0(); else CP_WAIT2();
        __syncthreads();   // group kc landed; mma(kc-1) done -> buf (kc+3)&3 is free
        if (kc < 29) {
            stage32(sb + ((kc + 3) & 3) * ST32, Ag + (kc + 3) * 32, Bg + (kc + 3) * 32, tid);
            CP_COMMIT();
        }
        uint32_t s = (kc & 3) * ST32;
        mma_block32(sb + s, sb + s + 10240, acc, lane, wm, wn);
    }
}

// ---------------- kernel: Q & K projection (z selects which) ----------------
__global__ void __launch_bounds__(256, 2) k_proj(const float* __restrict__ bq,
                                                 const float* __restrict__ bk) {
    extern __shared__ char sm[];
    uint32_t sb = smem_u32(sm);
    const int tid = threadIdx.x, lane = tid & 31, wid = tid >> 5;
    const int wm = (wid >> 2) * 64, wn = (wid & 3) * 32;
    const int b = blockIdx.y, r0 = blockIdx.x * 128, which = blockIdx.z;
    const __nv_bfloat16* W = which ? g_Wkb : g_Wqb;
    const float* bias = which ? bk : bq;
    __nv_bfloat16* outQ = (which ? g_Kb : g_Qb);

    float acc[4][4][4];
#pragma unroll
    for (int i = 0; i < 4; i++)
#pragma unroll
        for (int j = 0; j < 4; j++)
#pragma unroll
            for (int k = 0; k < 4; k++) acc[i][j][k] = 0.0f;

    gemm_1024(g_xT + ((size_t)b * SP + r0) * CH, W, sb, acc, tid, lane, wm, wn);

#pragma unroll
    for (int j = 0; j < 4; j++) {
        int col = wn + j * 8 + (lane & 3) * 2;
        float b0 = bias[col], b1 = bias[col + 1];
#pragma unroll
        for (int i = 0; i < 4; i++) {
            int rr = r0 + wm + i * 16 + (lane >> 2);
            *reinterpret_cast<__nv_bfloat162*>(&outQ[((size_t)b * SP + rr) * CQ + col]) =
                __floats2bfloat162_rn(acc[i][j][0] + b0, acc[i][j][1] + b1);
            *reinterpret_cast<__nv_bfloat162*>(&outQ[((size_t)b * SP + rr + 8) * CQ + col]) =
                __floats2bfloat162_rn(acc[i][j][2] + b0, acc[i][j][3] + b1);
        }
    }
}

// ---------------- kernel: energy + softmax, 64-row n-tiles (unchanged R6) ----------------
#define ELD 136
#define E_K0 17408
#define E_K1 52224
#define E_P  87040
#define E_SUM 105472
#define EN_SMEM 105984
__global__ void __launch_bounds__(256, 2) k_energy(const float* __restrict__ gm) {
    extern __shared__ char sm[];
    uint32_t sb = smem_u32(sm);
    float* s_sum = reinterpret_cast<float*>(sm + E_SUM);
    __nv_bfloat16* Ps = reinterpret_cast<__nv_bfloat16*>(sm + E_P);
    const int tid = threadIdx.x, lane = tid & 31, wid = tid >> 5;
    const int wnn = (wid >> 2) * 32, wmm = (wid & 3) * 32;
    const int b = blockIdx.y, n0 = blockIdx.x * 64;

    if (tid < 64) s_sum[tid] = 0.0f;

    const __nv_bfloat16* Qg = g_Qb + ((size_t)b * SP + n0) * CQ;
    const __nv_bfloat16* Kg = g_Kb + (size_t)b * SP * CQ;
#pragma unroll
    for (int u = 0; u < 4; u++) {
        int idx = tid + u * 256, r = idx >> 4, c = idx & 15;
        CP16(sb + r * 272 + c * 16, Qg + (size_t)r * CQ + c * 8);
    }
#pragma unroll
    for (int u = 0; u < 8; u++) {
        int idx = tid + u * 256, r = idx >> 4, c = idx & 15;
        CP16(sb + E_K0 + r * 272 + c * 16, Kg + (size_t)r * CQ + c * 8);
    }
    CP_COMMIT();
#pragma unroll
    for (int u = 0; u < 8; u++) {
        int idx = tid + u * 256, r = idx >> 4, c = idx & 15;
        CP16(sb + E_K1 + r * 272 + c * 16, Kg + (size_t)(128 + r) * CQ + c * 8);
    }
    CP_COMMIT();

#pragma unroll 1
    for (int mc = 0; mc < 8; mc++) {
        if (mc == 7) CP_WAIT0(); else CP_WAIT1();
        __syncthreads();
        const uint32_t kb = (mc & 1) ? E_K1 : E_K0;
        float acc[2][4][4];
#pragma unroll
        for (int i = 0; i < 2; i++)
#pragma unroll
            for (int j = 0; j < 4; j++)
#pragma unroll
                for (int k = 0; k < 4; k++) acc[i][j][k] = 0.0f;
#pragma unroll
        for (int ks = 0; ks < 8; ks++) {
            uint32_t a[2][4];
#pragma unroll
            for (int i = 0; i < 2; i++)
                ldm_x4(a[i], sb + ((wnn + i * 16 + (lane & 15)) * ELD
                                   + ks * 16 + ((lane >> 4) << 3)) * 2);
            uint32_t bf[2][4];
#pragma unroll
            for (int jp = 0; jp < 2; jp++)
                ldm_x4(bf[jp], sb + kb + ((wmm + jp * 16 + ((lane >> 4) << 3) + (lane & 7)) * ELD
                                          + ks * 16 + (((lane >> 3) & 1) << 3)) * 2);
#pragma unroll
            for (int i = 0; i < 2; i++)
#pragma unroll
                for (int j = 0; j < 4; j++)
                    mma16816(acc[i][j], a[i], bf[j >> 1][(j & 1) * 2], bf[j >> 1][(j & 1) * 2 + 1]);
        }
        __syncthreads();
        if (mc < 6) {
            const __nv_bfloat16* Kn = Kg + (size_t)(mc + 2) * 128 * CQ;
#pragma unroll
            for (int u = 0; u < 8; u++) {
                int idx = tid + u * 256, r = idx >> 4, c = idx & 15;
                CP16(sb + kb + r * 272 + c * 16, Kn + (size_t)r * CQ + c * 8);
            }
            CP_COMMIT();
        }
#pragma unroll
        for (int i = 0; i < 2; i++) {
            int nA = wnn + i * 16 + (lane >> 2), nB = nA + 8;
            float s0 = 0.0f, s1 = 0.0f;
#pragma unroll
            for (int j = 0; j < 4; j++) {
                int mcol = wmm + j * 8 + (lane & 3) * 2;
                float p0 = fast_exp(acc[i][j][0]), p1 = fast_exp(acc[i][j][1]);
                float p2 = fast_exp(acc[i][j][2]), p3 = fast_exp(acc[i][j][3]);
                s0 += p0 + p1; s1 += p2 + p3;
                Ps[(size_t)mcol * 72 + nA]       = __float2bfloat16(p0);
                Ps[(size_t)(mcol + 1) * 72 + nA] = __float2bfloat16(p1);
                Ps[(size_t)mcol * 72 + nB]       = __float2bfloat16(p2);
                Ps[(size_t)(mcol + 1) * 72 + nB] = __float2bfloat16(p3);
            }
            s0 += __shfl_xor_sync(0xffffffffu, s0, 1);
            s0 += __shfl_xor_sync(0xffffffffu, s0, 2);
            s1 += __shfl_xor_sync(0xffffffffu, s1, 1);
            s1 += __shfl_xor_sync(0xffffffffu, s1, 2);
            if ((lane & 3) == 0) { atomicAdd(&s_sum[nA], s0); atomicAdd(&s_sum[nB], s1); }
        }
        __syncthreads();
#pragma unroll
        for (int u = 0; u < 4; u++) {
            int idx = tid + u * 256, r = idx >> 3, c = idx & 7;
            uint4 v = *reinterpret_cast<uint4*>(sm + E_P + (r * 72 + c * 8) * 2);
            *reinterpret_cast<uint4*>(
                &g_P[((size_t)b * CH + mc * 128 + r) * SP + n0 + c * 8]) = v;
        }
    }
    __syncthreads();
    if (tid < 64)
        g_scale[(size_t)b * SP + n0 + tid] = gm[0] / s_sum[tid];
}

// ---------------- kernel: V GEMM fused with apply (direct epilogue) ----------------
__global__ void __launch_bounds__(256, 2) k_vapply(const float* __restrict__ bv,
                                                   const float* __restrict__ x,
                                                   float* __restrict__ out) {
    extern __shared__ char sm[];
    uint32_t sb = smem_u32(sm);
    const int tid = threadIdx.x, lane = tid & 31, wid = tid >> 5;
    const int wm = (wid >> 2) * 64, wn = (wid & 3) * 32;
    const int b = blockIdx.z, m0 = blockIdx.y * 128, n0 = blockIdx.x * 128;

    float acc[4][4][4];
#pragma unroll
    for (int i = 0; i < 4; i++)
#pragma unroll
        for (int j = 0; j < 4; j++)
#pragma unroll
            for (int k = 0; k < 4; k++) acc[i][j][k] = 0.0f;

    gemm_1024(g_Wvb + (size_t)m0 * CH, g_xT + ((size_t)b * SP + n0) * CH,
              sb, acc, tid, lane, wm, wn);

#pragma unroll
    for (int i = 0; i < 4; i++) {
        int mA = m0 + wm + i * 16 + (lane >> 2), mB = mA + 8;
        float bvA = bv[mA], bvB = bv[mB];
#pragma unroll
        for (int j = 0; j < 4; j++) {
            int n = n0 + wn + j * 8 + (lane & 3) * 2;
            size_t pa = ((size_t)b * CH + mA) * SP + n;
            size_t pb = ((size_t)b * CH + mB) * SP + n;
            float2 sc = *reinterpret_cast<const float2*>(&g_scale[(size_t)b * SP + n]);
            __nv_bfloat162 PA = *reinterpret_cast<const __nv_bfloat162*>(&g_P[pa]);
            __nv_bfloat162 PB = *reinterpret_cast<const __nv_bfloat162*>(&g_P[pb]);
            float2 xa = *reinterpret_cast<const float2*>(&x[pa]);
            float2 xb = *reinterpret_cast<const float2*>(&x[pb]);
            float2 oa, ob;
            oa.x = fmaf((acc[i][j][0] + bvA) * __bfloat162float(PA.x), sc.x, xa.x);
            oa.y = fmaf((acc[i][j][1] + bvA) * __bfloat162float(PA.y), sc.y, xa.y);
            ob.x = fmaf((acc[i][j][2] + bvB) * __bfloat162float(PB.x), sc.x, xb.x);
            ob.y = fmaf((acc[i][j][3] + bvB) * __bfloat162float(PB.y), sc.y, xb.y);
            *reinterpret_cast<float2*>(&out[pa]) = oa;
            *reinterpret_cast<float2*>(&out[pb]) = ob;
        }
    }
}

// ---------------- launcher ----------------
extern "C" void kernel_launch(void* const* d_in, const int* in_sizes, int n_in,
                              void* d_out, int out_size) {
    const float* x  = (const float*)d_in[0];
    const float* Wq = (const float*)d_in[1];
    const float* bq = (const float*)d_in[2];
    const float* Wk = (const float*)d_in[3];
    const float* bk = (const float*)d_in[4];
    const float* Wv = (const float*)d_in[5];
    const float* bv = (const float*)d_in[6];
    const float* gm = (const float*)d_in[7];
    float* out = (float*)d_out;

    cudaFuncSetAttribute(k_proj,   cudaFuncAttributeMaxDynamicSharedMemorySize, GEMM_SMEM);
    cudaFuncSetAttribute(k_vapply, cudaFuncAttributeMaxDynamicSharedMemorySize, GEMM_SMEM);
    cudaFuncSetAttribute(k_energy, cudaFuncAttributeMaxDynamicSharedMemorySize, EN_SMEM);

    k_cvtall<<<(2 * CQ * CH + CH * CH) / 1024, 256>>>(Wq, Wk, Wv);
    k_transpose<<<dim3(SP / 64, CH / 64, BB), 256>>>(x);
    k_proj<<<dim3(8, BB, 2), 256, GEMM_SMEM>>>(bq, bk);
    k_energy<<<dim3(SP / 64, BB), 256, EN_SMEM>>>(gm);
    k_vapply<<<dim3(8, 8, BB), 256, GEMM_SMEM>>>(bv, x, out);
}

// round 9
// speedup vs baseline: 1.1398x; 1.0857x over previous
#include <cuda_runtime.h>
#include <cuda_bf16.h>
#include <cstdint>

#define BB 32
#define CH 1024
#define SP 1024
#define CQ 128

// ---------------- scratch ----------------
__device__ __nv_bfloat16 g_xT[(size_t)BB * SP * CH];   // [b][n][c]
__device__ __nv_bfloat16 g_Qb[(size_t)BB * SP * CQ];   // [b][n][o]
__device__ __nv_bfloat16 g_Kb[(size_t)BB * SP * CQ];   // [b][m][o]
__device__ __nv_bfloat16 g_P [(size_t)BB * CH * SP];   // attT[b][m][n] = exp(e[n][m])
__device__ float         g_scale[(size_t)BB * SP];     // gamma / rowsum[n]
__device__ __nv_bfloat16 g_Wqb[CQ * CH];
__device__ __nv_bfloat16 g_Wkb[CQ * CH];
__device__ __nv_bfloat16 g_Wvb[(size_t)CH * CH];

// ---------------- helpers ----------------
__device__ __forceinline__ uint32_t smem_u32(const void* p) {
    uint32_t a;
    asm("{ .reg .u64 t; cvta.to.shared.u64 t, %1; cvt.u32.u64 %0, t; }" : "=r"(a) : "l"(p));
    return a;
}
#define CP16(d, s) \
    asm volatile("cp.async.cg.shared.global [%0], [%1], 16;" :: "r"(d), "l"(s) : "memory")
#define CP_COMMIT() asm volatile("cp.async.commit_group;" ::: "memory")
#define CP_WAIT0()  asm volatile("cp.async.wait_group 0;" ::: "memory")
#define CP_WAIT1()  asm volatile("cp.async.wait_group 1;" ::: "memory")

__device__ __forceinline__ void ldm_x4(uint32_t (&r)[4], uint32_t a) {
    asm volatile("ldmatrix.sync.aligned.m8n8.x4.shared.b16 {%0,%1,%2,%3}, [%4];"
        : "=r"(r[0]), "=r"(r[1]), "=r"(r[2]), "=r"(r[3]) : "r"(a));
}
__device__ __forceinline__ void mma16816(float (&c)[4], const uint32_t (&a)[4],
                                         uint32_t b0, uint32_t b1) {
    asm volatile(
        "mma.sync.aligned.m16n8k16.row.col.f32.bf16.bf16.f32 "
        "{%0,%1,%2,%3}, {%4,%5,%6,%7}, {%8,%9}, {%0,%1,%2,%3};"
        : "+f"(c[0]), "+f"(c[1]), "+f"(c[2]), "+f"(c[3])
        : "r"(a[0]), "r"(a[1]), "r"(a[2]), "r"(a[3]), "r"(b0), "r"(b1));
}
__device__ __forceinline__ float fast_exp(float x) {
    float t = fmaf(x, 12102203.0f, 1064866805.0f);
    return __int_as_float((int)t);
}

// ---------------- kernel: convert all weights fp32->bf16 ----------------
__global__ void k_cvtall(const float* __restrict__ Wq, const float* __restrict__ Wk,
                         const float* __restrict__ Wv) {
    int i = (blockIdx.x * 256 + threadIdx.x) * 4;
    const float* s; __nv_bfloat16* d; int off;
    if (i < CQ * CH)            { s = Wq; d = g_Wqb; off = i; }
    else if (i < 2 * CQ * CH)   { s = Wk; d = g_Wkb; off = i - CQ * CH; }
    else                        { s = Wv; d = g_Wvb; off = i - 2 * CQ * CH; }
    float4 v = *reinterpret_cast<const float4*>(s + off);
    *reinterpret_cast<__nv_bfloat162*>(d + off)     = __floats2bfloat162_rn(v.x, v.y);
    *reinterpret_cast<__nv_bfloat162*>(d + off + 2) = __floats2bfloat162_rn(v.z, v.w);
}

// ---------------- kernel: x[b][c][n] fp32 -> xT[b][n][c] bf16 (64x64 tiles) ----------------
__global__ void __launch_bounds__(256) k_transpose(const float* __restrict__ x) {
    __shared__ float ts[64][68];
    const int b = blockIdx.z, c0 = blockIdx.y * 64, n0 = blockIdx.x * 64;
    const int tid = threadIdx.x;
    {
        const int r = tid >> 4, c4 = (tid & 15) * 4;
        const float* src = x + ((size_t)b * CH + c0 + r) * SP + n0 + c4;
#pragma unroll
        for (int u = 0; u < 4; u++) {
            float4 v = *reinterpret_cast<const float4*>(src + (size_t)u * 16 * SP);
            ts[r + u * 16][c4] = v.x; ts[r + u * 16][c4 + 1] = v.y;
            ts[r + u * 16][c4 + 2] = v.z; ts[r + u * 16][c4 + 3] = v.w;
        }
    }
    __syncthreads();
    {
        const int ch = (tid & 7) * 8;
        __nv_bfloat16* dst = g_xT + ((size_t)b * SP + n0) * CH + c0 + ch;
#pragma unroll
        for (int u = 0; u < 2; u++) {
            int nn = (tid >> 3) + u * 32;
            __nv_bfloat162 h0 = __floats2bfloat162_rn(ts[ch][nn],     ts[ch + 1][nn]);
            __nv_bfloat162 h1 = __floats2bfloat162_rn(ts[ch + 2][nn], ts[ch + 3][nn]);
            __nv_bfloat162 h2 = __floats2bfloat162_rn(ts[ch + 4][nn], ts[ch + 5][nn]);
            __nv_bfloat162 h3 = __floats2bfloat162_rn(ts[ch + 6][nn], ts[ch + 7][nn]);
            uint4 o;
            o.x = *reinterpret_cast<uint32_t*>(&h0);
            o.y = *reinterpret_cast<uint32_t*>(&h1);
            o.z = *reinterpret_cast<uint32_t*>(&h2);
            o.w = *reinterpret_cast<uint32_t*>(&h3);
            *reinterpret_cast<uint4*>(dst + (size_t)nn * CH) = o;
        }
    }
}

// ---------------- GEMM core (R3-proven): 128x128 tile, K=1024, BK=64, 2-stage ----------------
#define GEMM_SMEM 73728
__device__ __forceinline__ void stage64(uint32_t sdst, const __nv_bfloat16* g, int tid) {
#pragma unroll
    for (int u = 0; u < 4; u++) {
        int idx = tid + u * 256, r = idx >> 3, c = idx & 7;
        CP16(sdst + r * 144 + c * 16, g + (size_t)r * CH + c * 8);
    }
}
__device__ __forceinline__ void mma_block64(uint32_t sA, uint32_t sB,
                                            float (&acc)[4][4][4], int lane, int wm, int wn) {
#pragma unroll
    for (int ks = 0; ks < 4; ks++) {
        uint32_t a[4][4];
#pragma unroll
        for (int i = 0; i < 4; i++)
            ldm_x4(a[i], sA + ((wm + i * 16 + (lane & 15)) * 72 + ks * 16 + ((lane >> 4) << 3)) * 2);
        uint32_t bf[2][4];
#pragma unroll
        for (int jp = 0; jp < 2; jp++)
            ldm_x4(bf[jp], sB + ((wn + jp * 16 + ((lane >> 4) << 3) + (lane & 7)) * 72
                                 + ks * 16 + (((lane >> 3) & 1) << 3)) * 2);
#pragma unroll
        for (int i = 0; i < 4; i++)
#pragma unroll
            for (int j = 0; j < 4; j++)
                mma16816(acc[i][j], a[i], bf[j >> 1][(j & 1) * 2], bf[j >> 1][(j & 1) * 2 + 1]);
    }
}
__device__ __forceinline__ void gemm_1024(const __nv_bfloat16* Ag, const __nv_bfloat16* Bg,
                                          uint32_t sb, float (&acc)[4][4][4],
                                          int tid, int lane, int wm, int wn) {
    const uint32_t sA0 = sb, sA1 = sb + 18432, sB0 = sb + 36864, sB1 = sb + 55296;
    stage64(sA0, Ag, tid);      stage64(sB0, Bg, tid);      CP_COMMIT();
    stage64(sA1, Ag + 64, tid); stage64(sB1, Bg + 64, tid); CP_COMMIT();
#pragma unroll 1
    for (int kc = 0; kc < 16; kc++) {
        if (kc >= 14) CP_WAIT0(); else CP_WAIT1();
        __syncthreads();
        mma_block64((kc & 1) ? sA1 : sA0, (kc & 1) ? sB1 : sB0, acc, lane, wm, wn);
        __syncthreads();
        if (kc < 14) {
            stage64((kc & 1) ? sA1 : sA0, Ag + (kc + 2) * 64, tid);
            stage64((kc & 1) ? sB1 : sB0, Bg + (kc + 2) * 64, tid);
            CP_COMMIT();
        }
    }
}

// ---------------- kernel: Q & K projection (z selects which) ----------------
__global__ void __launch_bounds__(256, 2) k_proj(const float* __restrict__ bq,
                                                 const float* __restrict__ bk) {
    extern __shared__ char sm[];
    uint32_t sb = smem_u32(sm);
    const int tid = threadIdx.x, lane = tid & 31, wid = tid >> 5;
    const int wm = (wid >> 2) * 64, wn = (wid & 3) * 32;
    const int b = blockIdx.y, r0 = blockIdx.x * 128, which = blockIdx.z;
    const __nv_bfloat16* W = which ? g_Wkb : g_Wqb;
    const float* bias = which ? bk : bq;
    __nv_bfloat16* outQ = (which ? g_Kb : g_Qb);

    float acc[4][4][4];
#pragma unroll
    for (int i = 0; i < 4; i++)
#pragma unroll
        for (int j = 0; j < 4; j++)
#pragma unroll
            for (int k = 0; k < 4; k++) acc[i][j][k] = 0.0f;

    gemm_1024(g_xT + ((size_t)b * SP + r0) * CH, W, sb, acc, tid, lane, wm, wn);

#pragma unroll
    for (int j = 0; j < 4; j++) {
        int col = wn + j * 8 + (lane & 3) * 2;
        float b0 = bias[col], b1 = bias[col + 1];
#pragma unroll
        for (int i = 0; i < 4; i++) {
            int rr = r0 + wm + i * 16 + (lane >> 2);
            *reinterpret_cast<__nv_bfloat162*>(&outQ[((size_t)b * SP + rr) * CQ + col]) =
                __floats2bfloat162_rn(acc[i][j][0] + b0, acc[i][j][1] + b1);
            *reinterpret_cast<__nv_bfloat162*>(&outQ[((size_t)b * SP + rr + 8) * CQ + col]) =
                __floats2bfloat162_rn(acc[i][j][2] + b0, acc[i][j][3] + b1);
        }
    }
}

// ---------------- kernel: energy + softmax (R3 version: 128-row tiles, epilogue-overlapped K) ----
#define ELD 136
#define EA 0
#define EB 34816
#define EP 69632
#define ESUM 104448
#define EN_SMEM 104960
__global__ void __launch_bounds__(256, 2) k_energy(const float* __restrict__ gm) {
    extern __shared__ char sm[];
    uint32_t sb = smem_u32(sm);
    float* s_sum = reinterpret_cast<float*>(sm + ESUM);
    __nv_bfloat16* Ps = reinterpret_cast<__nv_bfloat16*>(sm + EP);
    const int tid = threadIdx.x, lane = tid & 31, wid = tid >> 5;
    const int wnn = (wid >> 2) * 64, wmm = (wid & 3) * 32;
    const int b = blockIdx.y, n0 = blockIdx.x * 128;

    if (tid < 128) s_sum[tid] = 0.0f;

    const __nv_bfloat16* Qg = g_Qb + ((size_t)b * SP + n0) * CQ;
    const __nv_bfloat16* Kg = g_Kb + (size_t)b * SP * CQ;
#pragma unroll
    for (int u = 0; u < 8; u++) {
        int idx = tid + u * 256, r = idx >> 4, c = idx & 15;
        CP16(sb + EA + r * 272 + c * 16, Qg + (size_t)r * CQ + c * 8);
        CP16(sb + EB + r * 272 + c * 16, Kg + (size_t)r * CQ + c * 8);
    }
    CP_COMMIT();

#pragma unroll 1
    for (int mc = 0; mc < 8; mc++) {
        CP_WAIT0();
        __syncthreads();
        float acc[4][4][4];
#pragma unroll
        for (int i = 0; i < 4; i++)
#pragma unroll
            for (int j = 0; j < 4; j++)
#pragma unroll
                for (int k = 0; k < 4; k++) acc[i][j][k] = 0.0f;
#pragma unroll
        for (int ks = 0; ks < 8; ks++) {
            uint32_t a[4][4];
#pragma unroll
            for (int i = 0; i < 4; i++)
                ldm_x4(a[i], sb + EA + ((wnn + i * 16 + (lane & 15)) * ELD
                                        + ks * 16 + ((lane >> 4) << 3)) * 2);
            uint32_t bf[2][4];
#pragma unroll
            for (int jp = 0; jp < 2; jp++)
                ldm_x4(bf[jp], sb + EB + ((wmm + jp * 16 + ((lane >> 4) << 3) + (lane & 7)) * ELD
                                          + ks * 16 + (((lane >> 3) & 1) << 3)) * 2);
#pragma unroll
            for (int i = 0; i < 4; i++)
#pragma unroll
                for (int j = 0; j < 4; j++)
                    mma16816(acc[i][j], a[i], bf[j >> 1][(j & 1) * 2], bf[j >> 1][(j & 1) * 2 + 1]);
        }
        __syncthreads();
        if (mc < 7) {   // prefetch next K tile; latency hidden by the epilogue below
            const __nv_bfloat16* Kn = Kg + (size_t)(mc + 1) * 128 * CQ;
#pragma unroll
            for (int u = 0; u < 8; u++) {
                int idx = tid + u * 256, r = idx >> 4, c = idx & 15;
                CP16(sb + EB + r * 272 + c * 16, Kn + (size_t)r * CQ + c * 8);
            }
            CP_COMMIT();
        }
        // epilogue: exp -> Ps[m][n] (transposed in smem), rowsum
#pragma unroll
        for (int i = 0; i < 4; i++) {
            int nA = wnn + i * 16 + (lane >> 2), nB = nA + 8;
            float s0 = 0.0f, s1 = 0.0f;
#pragma unroll
            for (int j = 0; j < 4; j++) {
                int mcol = wmm + j * 8 + (lane & 3) * 2;
                float p0 = fast_exp(acc[i][j][0]), p1 = fast_exp(acc[i][j][1]);
                float p2 = fast_exp(acc[i][j][2]), p3 = fast_exp(acc[i][j][3]);
                s0 += p0 + p1; s1 += p2 + p3;
                Ps[(size_t)mcol * ELD + nA]       = __float2bfloat16(p0);
                Ps[(size_t)(mcol + 1) * ELD + nA] = __float2bfloat16(p1);
                Ps[(size_t)mcol * ELD + nB]       = __float2bfloat16(p2);
                Ps[(size_t)(mcol + 1) * ELD + nB] = __float2bfloat16(p3);
            }
            s0 += __shfl_xor_sync(0xffffffffu, s0, 1);
            s0 += __shfl_xor_sync(0xffffffffu, s0, 2);
            s1 += __shfl_xor_sync(0xffffffffu, s1, 1);
            s1 += __shfl_xor_sync(0xffffffffu, s1, 2);
            if ((lane & 3) == 0) { atomicAdd(&s_sum[nA], s0); atomicAdd(&s_sum[nB], s1); }
        }
        __syncthreads();
#pragma unroll
        for (int u = 0; u < 8; u++) {
            int idx = tid + u * 256, r = idx >> 4, c = idx & 15;
            uint4 v = *reinterpret_cast<uint4*>(sm + EP + r * 272 + c * 16);
            *reinterpret_cast<uint4*>(
                &g_P[((size_t)b * CH + mc * 128 + r) * SP + n0 + c * 8]) = v;
        }
    }
    __syncthreads();
    if (tid < 128)
        g_scale[(size_t)b * SP + n0 + tid] = gm[0] / s_sum[tid];
}

// ---------------- kernel: V GEMM fused with apply (direct epilogue) ----------------
__global__ void __launch_bounds__(256, 2) k_vapply(const float* __restrict__ bv,
                                                   const float* __restrict__ x,
                                                   float* __restrict__ out) {
    extern __shared__ char sm[];
    uint32_t sb = smem_u32(sm);
    const int tid = threadIdx.x, lane = tid & 31, wid = tid >> 5;
    const int wm = (wid >> 2) * 64, wn = (wid & 3) * 32;
    const int b = blockIdx.z, m0 = blockIdx.y * 128, n0 = blockIdx.x * 128;

    float acc[4][4][4];
#pragma unroll
    for (int i = 0; i < 4; i++)
#pragma unroll
        for (int j = 0; j < 4; j++)
#pragma unroll
            for (int k = 0; k < 4; k++) acc[i][j][k] = 0.0f;

    gemm_1024(g_Wvb + (size_t)m0 * CH, g_xT + ((size_t)b * SP + n0) * CH,
              sb, acc, tid, lane, wm, wn);

#pragma unroll
    for (int i = 0; i < 4; i++) {
        int mA = m0 + wm + i * 16 + (lane >> 2), mB = mA + 8;
        float bvA = bv[mA], bvB = bv[mB];
#pragma unroll
        for (int j = 0; j < 4; j++) {
            int n = n0 + wn + j * 8 + (lane & 3) * 2;
            size_t pa = ((size_t)b * CH + mA) * SP + n;
            size_t pb = ((size_t)b * CH + mB) * SP + n;
            float2 sc = *reinterpret_cast<const float2*>(&g_scale[(size_t)b * SP + n]);
            __nv_bfloat162 PA = *reinterpret_cast<const __nv_bfloat162*>(&g_P[pa]);
            __nv_bfloat162 PB = *reinterpret_cast<const __nv_bfloat162*>(&g_P[pb]);
            float2 xa = *reinterpret_cast<const float2*>(&x[pa]);
            float2 xb = *reinterpret_cast<const float2*>(&x[pb]);
            float2 oa, ob;
            oa.x = fmaf((acc[i][j][0] + bvA) * __bfloat162float(PA.x), sc.x, xa.x);
            oa.y = fmaf((acc[i][j][1] + bvA) * __bfloat162float(PA.y), sc.y, xa.y);
            ob.x = fmaf((acc[i][j][2] + bvB) * __bfloat162float(PB.x), sc.x, xb.x);
            ob.y = fmaf((acc[i][j][3] + bvB) * __bfloat162float(PB.y), sc.y, xb.y);
            *reinterpret_cast<float2*>(&out[pa]) = oa;
            *reinterpret_cast<float2*>(&out[pb]) = ob;
        }
    }
}

// ---------------- launcher ----------------
extern "C" void kernel_launch(void* const* d_in, const int* in_sizes, int n_in,
                              void* d_out, int out_size) {
    const float* x  = (const float*)d_in[0];
    const float* Wq = (const float*)d_in[1];
    const float* bq = (const float*)d_in[2];
    const float* Wk = (const float*)d_in[3];
    const float* bk = (const float*)d_in[4];
    const float* Wv = (const float*)d_in[5];
    const float* bv = (const float*)d_in[6];
    const float* gm = (const float*)d_in[7];
    float* out = (float*)d_out;

    cudaFuncSetAttribute(k_proj,   cudaFuncAttributeMaxDynamicSharedMemorySize, GEMM_SMEM);
    cudaFuncSetAttribute(k_vapply, cudaFuncAttributeMaxDynamicSharedMemorySize, GEMM_SMEM);
    cudaFuncSetAttribute(k_energy, cudaFuncAttributeMaxDynamicSharedMemorySize, EN_SMEM);

    k_cvtall<<<(2 * CQ * CH + CH * CH) / 1024, 256>>>(Wq, Wk, Wv);
    k_transpose<<<dim3(SP / 64, CH / 64, BB), 256>>>(x);
    k_proj<<<dim3(8, BB, 2), 256, GEMM_SMEM>>>(bq, bk);
    k_energy<<<dim3(8, BB), 256, EN_SMEM>>>(gm);
    k_vapply<<<dim3(8, 8, BB), 256, GEMM_SMEM>>>(bv, x, out);
}

// round 10
// speedup vs baseline: 1.1645x; 1.0217x over previous
#include <cuda_runtime.h>
#include <cuda_bf16.h>
#include <cstdint>

#define BB 32
#define CH 1024
#define SP 1024
#define CQ 128

// ---------------- scratch ----------------
__device__ __nv_bfloat16 g_xT[(size_t)BB * SP * CH];   // [b][n][c] bf16
__device__ uint8_t       g_xT8[(size_t)BB * SP * CH];  // [b][n][c] e4m3
__device__ __nv_bfloat16 g_Qb[(size_t)BB * SP * CQ];   // [b][n][o]
__device__ __nv_bfloat16 g_Kb[(size_t)BB * SP * CQ];   // [b][m][o]
__device__ __nv_bfloat16 g_P [(size_t)BB * CH * SP];   // attT[b][m][n] = exp(e[n][m])
__device__ float         g_scale[(size_t)BB * SP];     // gamma / (64 * rowsum[n])
__device__ __nv_bfloat16 g_Wqb[CQ * CH];
__device__ __nv_bfloat16 g_Wkb[CQ * CH];
__device__ uint8_t       g_Wv8[(size_t)CH * CH];       // e4m3, scaled by 64

// ---------------- helpers ----------------
__device__ __forceinline__ uint32_t smem_u32(const void* p) {
    uint32_t a;
    asm("{ .reg .u64 t; cvta.to.shared.u64 t, %1; cvt.u32.u64 %0, t; }" : "=r"(a) : "l"(p));
    return a;
}
#define CP16(d, s) \
    asm volatile("cp.async.cg.shared.global [%0], [%1], 16;" :: "r"(d), "l"(s) : "memory")
#define CP_COMMIT() asm volatile("cp.async.commit_group;" ::: "memory")
#define CP_WAIT0()  asm volatile("cp.async.wait_group 0;" ::: "memory")
#define CP_WAIT1()  asm volatile("cp.async.wait_group 1;" ::: "memory")

__device__ __forceinline__ void ldm_x4(uint32_t (&r)[4], uint32_t a) {
    asm volatile("ldmatrix.sync.aligned.m8n8.x4.shared.b16 {%0,%1,%2,%3}, [%4];"
        : "=r"(r[0]), "=r"(r[1]), "=r"(r[2]), "=r"(r[3]) : "r"(a));
}
__device__ __forceinline__ void mma16816(float (&c)[4], const uint32_t (&a)[4],
                                         uint32_t b0, uint32_t b1) {
    asm volatile(
        "mma.sync.aligned.m16n8k16.row.col.f32.bf16.bf16.f32 "
        "{%0,%1,%2,%3}, {%4,%5,%6,%7}, {%8,%9}, {%0,%1,%2,%3};"
        : "+f"(c[0]), "+f"(c[1]), "+f"(c[2]), "+f"(c[3])
        : "r"(a[0]), "r"(a[1]), "r"(a[2]), "r"(a[3]), "r"(b0), "r"(b1));
}
__device__ __forceinline__ void mma16832q(float (&c)[4], const uint32_t (&a)[4],
                                          uint32_t b0, uint32_t b1) {
    asm volatile(
        "mma.sync.aligned.m16n8k32.row.col.f32.e4m3.e4m3.f32 "
        "{%0,%1,%2,%3}, {%4,%5,%6,%7}, {%8,%9}, {%0,%1,%2,%3};"
        : "+f"(c[0]), "+f"(c[1]), "+f"(c[2]), "+f"(c[3])
        : "r"(a[0]), "r"(a[1]), "r"(a[2]), "r"(a[3]), "r"(b0), "r"(b1));
}
__device__ __forceinline__ float fast_exp(float x) {
    float t = fmaf(x, 12102203.0f, 1064866805.0f);
    return __int_as_float((int)t);
}
// pack 4 floats -> 4 e4m3 bytes (memory order a,b,c,d)
__device__ __forceinline__ uint32_t pack_e4m3_4(float a, float b, float c, float d) {
    uint16_t lo, hi;
    asm("cvt.rn.satfinite.e4m3x2.f32 %0, %1, %2;" : "=h"(lo) : "f"(b), "f"(a));
    asm("cvt.rn.satfinite.e4m3x2.f32 %0, %1, %2;" : "=h"(hi) : "f"(d), "f"(c));
    return (uint32_t)lo | ((uint32_t)hi << 16);
}

// ---------------- kernel: convert weights (Wq/Wk bf16, Wv e4m3 x64) ----------------
__global__ void k_cvtall(const float* __restrict__ Wq, const float* __restrict__ Wk,
                         const float* __restrict__ Wv) {
    const int QK = CQ * CH;
    int i = (blockIdx.x * 256 + threadIdx.x) * 4;
    if (i < 2 * QK) {
        const float* s = (i < QK) ? Wq : Wk;
        __nv_bfloat16* d = (i < QK) ? g_Wqb : g_Wkb;
        int off = (i < QK) ? i : i - QK;
        float4 v = *reinterpret_cast<const float4*>(s + off);
        *reinterpret_cast<__nv_bfloat162*>(d + off)     = __floats2bfloat162_rn(v.x, v.y);
        *reinterpret_cast<__nv_bfloat162*>(d + off + 2) = __floats2bfloat162_rn(v.z, v.w);
    } else {
        int off = i - 2 * QK;
        float4 v = *reinterpret_cast<const float4*>(Wv + off);
        *reinterpret_cast<uint32_t*>(g_Wv8 + off) =
            pack_e4m3_4(v.x * 64.0f, v.y * 64.0f, v.z * 64.0f, v.w * 64.0f);
    }
}

// ---------------- kernel: x[b][c][n] fp32 -> xT bf16 + e4m3 (64x64 tiles) ----------------
__global__ void __launch_bounds__(256) k_transpose(const float* __restrict__ x) {
    __shared__ float ts[64][68];
    const int b = blockIdx.z, c0 = blockIdx.y * 64, n0 = blockIdx.x * 64;
    const int tid = threadIdx.x;
    {
        const int r = tid >> 4, c4 = (tid & 15) * 4;
        const float* src = x + ((size_t)b * CH + c0 + r) * SP + n0 + c4;
#pragma unroll
        for (int u = 0; u < 4; u++) {
            float4 v = *reinterpret_cast<const float4*>(src + (size_t)u * 16 * SP);
            ts[r + u * 16][c4] = v.x; ts[r + u * 16][c4 + 1] = v.y;
            ts[r + u * 16][c4 + 2] = v.z; ts[r + u * 16][c4 + 3] = v.w;
        }
    }
    __syncthreads();
    {
        const int ch = (tid & 7) * 8;
#pragma unroll
        for (int u = 0; u < 2; u++) {
            int nn = (tid >> 3) + u * 32;
            float f0 = ts[ch][nn],     f1 = ts[ch + 1][nn];
            float f2 = ts[ch + 2][nn], f3 = ts[ch + 3][nn];
            float f4 = ts[ch + 4][nn], f5 = ts[ch + 5][nn];
            float f6 = ts[ch + 6][nn], f7 = ts[ch + 7][nn];
            __nv_bfloat162 h0 = __floats2bfloat162_rn(f0, f1);
            __nv_bfloat162 h1 = __floats2bfloat162_rn(f2, f3);
            __nv_bfloat162 h2 = __floats2bfloat162_rn(f4, f5);
            __nv_bfloat162 h3 = __floats2bfloat162_rn(f6, f7);
            uint4 o;
            o.x = *reinterpret_cast<uint32_t*>(&h0);
            o.y = *reinterpret_cast<uint32_t*>(&h1);
            o.z = *reinterpret_cast<uint32_t*>(&h2);
            o.w = *reinterpret_cast<uint32_t*>(&h3);
            size_t base = ((size_t)b * SP + n0 + nn) * CH + c0 + ch;
            *reinterpret_cast<uint4*>(g_xT + base) = o;
            uint2 o8;
            o8.x = pack_e4m3_4(f0, f1, f2, f3);
            o8.y = pack_e4m3_4(f4, f5, f6, f7);
            *reinterpret_cast<uint2*>(g_xT8 + base) = o8;
        }
    }
}

// ---------------- bf16 GEMM core (R3-proven): 128x128, BK=64, 2-stage ----------------
#define GEMM_SMEM 73728
__device__ __forceinline__ void stage64(uint32_t sdst, const __nv_bfloat16* g, int tid) {
#pragma unroll
    for (int u = 0; u < 4; u++) {
        int idx = tid + u * 256, r = idx >> 3, c = idx & 7;
        CP16(sdst + r * 144 + c * 16, g + (size_t)r * CH + c * 8);
    }
}
__device__ __forceinline__ void mma_block64(uint32_t sA, uint32_t sB,
                                            float (&acc)[4][4][4], int lane, int wm, int wn) {
#pragma unroll
    for (int ks = 0; ks < 4; ks++) {
        uint32_t a[4][4];
#pragma unroll
        for (int i = 0; i < 4; i++)
            ldm_x4(a[i], sA + ((wm + i * 16 + (lane & 15)) * 72 + ks * 16 + ((lane >> 4) << 3)) * 2);
        uint32_t bf[2][4];
#pragma unroll
        for (int jp = 0; jp < 2; jp++)
            ldm_x4(bf[jp], sB + ((wn + jp * 16 + ((lane >> 4) << 3) + (lane & 7)) * 72
                                 + ks * 16 + (((lane >> 3) & 1) << 3)) * 2);
#pragma unroll
        for (int i = 0; i < 4; i++)
#pragma unroll
            for (int j = 0; j < 4; j++)
                mma16816(acc[i][j], a[i], bf[j >> 1][(j & 1) * 2], bf[j >> 1][(j & 1) * 2 + 1]);
    }
}
__device__ __forceinline__ void gemm_1024(const __nv_bfloat16* Ag, const __nv_bfloat16* Bg,
                                          uint32_t sb, float (&acc)[4][4][4],
                                          int tid, int lane, int wm, int wn) {
    const uint32_t sA0 = sb, sA1 = sb + 18432, sB0 = sb + 36864, sB1 = sb + 55296;
    stage64(sA0, Ag, tid);      stage64(sB0, Bg, tid);      CP_COMMIT();
    stage64(sA1, Ag + 64, tid); stage64(sB1, Bg + 64, tid); CP_COMMIT();
#pragma unroll 1
    for (int kc = 0; kc < 16; kc++) {
        if (kc >= 14) CP_WAIT0(); else CP_WAIT1();
        __syncthreads();
        mma_block64((kc & 1) ? sA1 : sA0, (kc & 1) ? sB1 : sB0, acc, lane, wm, wn);
        __syncthreads();
        if (kc < 14) {
            stage64((kc & 1) ? sA1 : sA0, Ag + (kc + 2) * 64, tid);
            stage64((kc & 1) ? sB1 : sB0, Bg + (kc + 2) * 64, tid);
            CP_COMMIT();
        }
    }
}

// ---------------- kernel: Q & K projection (bf16, z selects which) ----------------
__global__ void __launch_bounds__(256, 2) k_proj(const float* __restrict__ bq,
                                                 const float* __restrict__ bk) {
    extern __shared__ char sm[];
    uint32_t sb = smem_u32(sm);
    const int tid = threadIdx.x, lane = tid & 31, wid = tid >> 5;
    const int wm = (wid >> 2) * 64, wn = (wid & 3) * 32;
    const int b = blockIdx.y, r0 = blockIdx.x * 128, which = blockIdx.z;
    const __nv_bfloat16* W = which ? g_Wkb : g_Wqb;
    const float* bias = which ? bk : bq;
    __nv_bfloat16* outQ = (which ? g_Kb : g_Qb);

    float acc[4][4][4];
#pragma unroll
    for (int i = 0; i < 4; i++)
#pragma unroll
        for (int j = 0; j < 4; j++)
#pragma unroll
            for (int k = 0; k < 4; k++) acc[i][j][k] = 0.0f;

    gemm_1024(g_xT + ((size_t)b * SP + r0) * CH, W, sb, acc, tid, lane, wm, wn);

#pragma unroll
    for (int j = 0; j < 4; j++) {
        int col = wn + j * 8 + (lane & 3) * 2;
        float b0 = bias[col], b1 = bias[col + 1];
#pragma unroll
        for (int i = 0; i < 4; i++) {
            int rr = r0 + wm + i * 16 + (lane >> 2);
            *reinterpret_cast<__nv_bfloat162*>(&outQ[((size_t)b * SP + rr) * CQ + col]) =
                __floats2bfloat162_rn(acc[i][j][0] + b0, acc[i][j][1] + b1);
            *reinterpret_cast<__nv_bfloat162*>(&outQ[((size_t)b * SP + rr + 8) * CQ + col]) =
                __floats2bfloat162_rn(acc[i][j][2] + b0, acc[i][j][3] + b1);
        }
    }
}

// ---------------- kernel: energy + softmax (R3 proven: 128-row tiles) ----------------
#define ELD 136
#define EA 0
#define EB 34816
#define EP 69632
#define ESUM 104448
#define EN_SMEM 104960
__global__ void __launch_bounds__(256, 2) k_energy(const float* __restrict__ gm) {
    extern __shared__ char sm[];
    uint32_t sb = smem_u32(sm);
    float* s_sum = reinterpret_cast<float*>(sm + ESUM);
    __nv_bfloat16* Ps = reinterpret_cast<__nv_bfloat16*>(sm + EP);
    const int tid = threadIdx.x, lane = tid & 31, wid = tid >> 5;
    const int wnn = (wid >> 2) * 64, wmm = (wid & 3) * 32;
    const int b = blockIdx.y, n0 = blockIdx.x * 128;

    if (tid < 128) s_sum[tid] = 0.0f;

    const __nv_bfloat16* Qg = g_Qb + ((size_t)b * SP + n0) * CQ;
    const __nv_bfloat16* Kg = g_Kb + (size_t)b * SP * CQ;
#pragma unroll
    for (int u = 0; u < 8; u++) {
        int idx = tid + u * 256, r = idx >> 4, c = idx & 15;
        CP16(sb + EA + r * 272 + c * 16, Qg + (size_t)r * CQ + c * 8);
        CP16(sb + EB + r * 272 + c * 16, Kg + (size_t)r * CQ + c * 8);
    }
    CP_COMMIT();

#pragma unroll 1
    for (int mc = 0; mc < 8; mc++) {
        CP_WAIT0();
        __syncthreads();
        float acc[4][4][4];
#pragma unroll
        for (int i = 0; i < 4; i++)
#pragma unroll
            for (int j = 0; j < 4; j++)
#pragma unroll
                for (int k = 0; k < 4; k++) acc[i][j][k] = 0.0f;
#pragma unroll
        for (int ks = 0; ks < 8; ks++) {
            uint32_t a[4][4];
#pragma unroll
            for (int i = 0; i < 4; i++)
                ldm_x4(a[i], sb + EA + ((wnn + i * 16 + (lane & 15)) * ELD
                                        + ks * 16 + ((lane >> 4) << 3)) * 2);
            uint32_t bf[2][4];
#pragma unroll
            for (int jp = 0; jp < 2; jp++)
                ldm_x4(bf[jp], sb + EB + ((wmm + jp * 16 + ((lane >> 4) << 3) + (lane & 7)) * ELD
                                          + ks * 16 + (((lane >> 3) & 1) << 3)) * 2);
#pragma unroll
            for (int i = 0; i < 4; i++)
#pragma unroll
                for (int j = 0; j < 4; j++)
                    mma16816(acc[i][j], a[i], bf[j >> 1][(j & 1) * 2], bf[j >> 1][(j & 1) * 2 + 1]);
        }
        __syncthreads();
        if (mc < 7) {
            const __nv_bfloat16* Kn = Kg + (size_t)(mc + 1) * 128 * CQ;
#pragma unroll
            for (int u = 0; u < 8; u++) {
                int idx = tid + u * 256, r = idx >> 4, c = idx & 15;
                CP16(sb + EB + r * 272 + c * 16, Kn + (size_t)r * CQ + c * 8);
            }
            CP_COMMIT();
        }
#pragma unroll
        for (int i = 0; i < 4; i++) {
            int nA = wnn + i * 16 + (lane >> 2), nB = nA + 8;
            float s0 = 0.0f, s1 = 0.0f;
#pragma unroll
            for (int j = 0; j < 4; j++) {
                int mcol = wmm + j * 8 + (lane & 3) * 2;
                float p0 = fast_exp(acc[i][j][0]), p1 = fast_exp(acc[i][j][1]);
                float p2 = fast_exp(acc[i][j][2]), p3 = fast_exp(acc[i][j][3]);
                s0 += p0 + p1; s1 += p2 + p3;
                Ps[(size_t)mcol * ELD + nA]       = __float2bfloat16(p0);
                Ps[(size_t)(mcol + 1) * ELD + nA] = __float2bfloat16(p1);
                Ps[(size_t)mcol * ELD + nB]       = __float2bfloat16(p2);
                Ps[(size_t)(mcol + 1) * ELD + nB] = __float2bfloat16(p3);
            }
            s0 += __shfl_xor_sync(0xffffffffu, s0, 1);
            s0 += __shfl_xor_sync(0xffffffffu, s0, 2);
            s1 += __shfl_xor_sync(0xffffffffu, s1, 1);
            s1 += __shfl_xor_sync(0xffffffffu, s1, 2);
            if ((lane & 3) == 0) { atomicAdd(&s_sum[nA], s0); atomicAdd(&s_sum[nB], s1); }
        }
        __syncthreads();
#pragma unroll
        for (int u = 0; u < 8; u++) {
            int idx = tid + u * 256, r = idx >> 4, c = idx & 15;
            uint4 v = *reinterpret_cast<uint4*>(sm + EP + r * 272 + c * 16);
            *reinterpret_cast<uint4*>(
                &g_P[((size_t)b * CH + mc * 128 + r) * SP + n0 + c * 8]) = v;
        }
    }
    __syncthreads();
    if (tid < 128)   // 1/64 folds the Wv fp8 scaling; bv is scaled by 64 in k_vapply
        g_scale[(size_t)b * SP + n0 + tid] = gm[0] * 0.015625f / s_sum[tid];
}

// ---------------- kernel: V GEMM in FP8 (m16n8k32 e4m3) fused with apply ----------------
__device__ __forceinline__ void stage128q(uint32_t sdst, const uint8_t* g, int tid) {
#pragma unroll
    for (int u = 0; u < 4; u++) {
        int idx = tid + u * 256, r = idx >> 3, c = idx & 7;
        CP16(sdst + r * 144 + c * 16, g + (size_t)r * CH + c * 16);
    }
}
__device__ __forceinline__ void mma_block128q(uint32_t sA, uint32_t sB,
                                              float (&acc)[4][4][4], int lane, int wm, int wn) {
#pragma unroll
    for (int ks = 0; ks < 4; ks++) {
        uint32_t a[4][4];
#pragma unroll
        for (int i = 0; i < 4; i++)
            ldm_x4(a[i], sA + (wm + i * 16 + (lane & 15)) * 144 + ks * 32 + ((lane >> 4) << 4));
        uint32_t bf[2][4];
#pragma unroll
        for (int jp = 0; jp < 2; jp++)
            ldm_x4(bf[jp], sB + (wn + jp * 16 + ((lane >> 4) << 3) + (lane & 7)) * 144
                              + ks * 32 + (((lane >> 3) & 1) << 4));
#pragma unroll
        for (int i = 0; i < 4; i++)
#pragma unroll
            for (int j = 0; j < 4; j++)
                mma16832q(acc[i][j], a[i], bf[j >> 1][(j & 1) * 2], bf[j >> 1][(j & 1) * 2 + 1]);
    }
}
__global__ void __launch_bounds__(256, 2) k_vapply(const float* __restrict__ bv,
                                                   const float* __restrict__ x,
                                                   float* __restrict__ out) {
    extern __shared__ char sm[];
    uint32_t sb = smem_u32(sm);
    const int tid = threadIdx.x, lane = tid & 31, wid = tid >> 5;
    const int wm = (wid >> 2) * 64, wn = (wid & 3) * 32;
    const int b = blockIdx.z, m0 = blockIdx.y * 128, n0 = blockIdx.x * 128;

    float acc[4][4][4];
#pragma unroll
    for (int i = 0; i < 4; i++)
#pragma unroll
        for (int j = 0; j < 4; j++)
#pragma unroll
            for (int k = 0; k < 4; k++) acc[i][j][k] = 0.0f;

    const uint8_t* Ag = g_Wv8 + (size_t)m0 * CH;
    const uint8_t* Bg = g_xT8 + ((size_t)b * SP + n0) * CH;
    const uint32_t sA0 = sb, sA1 = sb + 18432, sB0 = sb + 36864, sB1 = sb + 55296;
    stage128q(sA0, Ag, tid);       stage128q(sB0, Bg, tid);       CP_COMMIT();
    stage128q(sA1, Ag + 128, tid); stage128q(sB1, Bg + 128, tid); CP_COMMIT();
#pragma unroll 1
    for (int kc = 0; kc < 8; kc++) {
        if (kc >= 6) CP_WAIT0(); else CP_WAIT1();
        __syncthreads();
        mma_block128q((kc & 1) ? sA1 : sA0, (kc & 1) ? sB1 : sB0, acc, lane, wm, wn);
        __syncthreads();
        if (kc < 6) {
            stage128q((kc & 1) ? sA1 : sA0, Ag + (kc + 2) * 128, tid);
            stage128q((kc & 1) ? sB1 : sB0, Bg + (kc + 2) * 128, tid);
            CP_COMMIT();
        }
    }

#pragma unroll
    for (int i = 0; i < 4; i++) {
        int mA = m0 + wm + i * 16 + (lane >> 2), mB = mA + 8;
        float bvA = bv[mA] * 64.0f, bvB = bv[mB] * 64.0f;   // g_scale carries the 1/64
#pragma unroll
        for (int j = 0; j < 4; j++) {
            int n = n0 + wn + j * 8 + (lane & 3) * 2;
            size_t pa = ((size_t)b * CH + mA) * SP + n;
            size_t pb = ((size_t)b * CH + mB) * SP + n;
            float2 sc = *reinterpret_cast<const float2*>(&g_scale[(size_t)b * SP + n]);
            __nv_bfloat162 PA = *reinterpret_cast<const __nv_bfloat162*>(&g_P[pa]);
            __nv_bfloat162 PB = *reinterpret_cast<const __nv_bfloat162*>(&g_P[pb]);
            float2 xa = *reinterpret_cast<const float2*>(&x[pa]);
            float2 xb = *reinterpret_cast<const float2*>(&x[pb]);
            float2 oa, ob;
            oa.x = fmaf((acc[i][j][0] + bvA) * __bfloat162float(PA.x), sc.x, xa.x);
            oa.y = fmaf((acc[i][j][1] + bvA) * __bfloat162float(PA.y), sc.y, xa.y);
            ob.x = fmaf((acc[i][j][2] + bvB) * __bfloat162float(PB.x), sc.x, xb.x);
            ob.y = fmaf((acc[i][j][3] + bvB) * __bfloat162float(PB.y), sc.y, xb.y);
            *reinterpret_cast<float2*>(&out[pa]) = oa;
            *reinterpret_cast<float2*>(&out[pb]) = ob;
        }
    }
}

// ---------------- launcher ----------------
extern "C" void kernel_launch(void* const* d_in, const int* in_sizes, int n_in,
                              void* d_out, int out_size) {
    const float* x  = (const float*)d_in[0];
    const float* Wq = (const float*)d_in[1];
    const float* bq = (const float*)d_in[2];
    const float* Wk = (const float*)d_in[3];
    const float* bk = (const float*)d_in[4];
    const float* Wv = (const float*)d_in[5];
    const float* bv = (const float*)d_in[6];
    const float* gm = (const float*)d_in[7];
    float* out = (float*)d_out;

    cudaFuncSetAttribute(k_proj,   cudaFuncAttributeMaxDynamicSharedMemorySize, GEMM_SMEM);
    cudaFuncSetAttribute(k_vapply, cudaFuncAttributeMaxDynamicSharedMemorySize, GEMM_SMEM);
    cudaFuncSetAttribute(k_energy, cudaFuncAttributeMaxDynamicSharedMemorySize, EN_SMEM);

    k_cvtall<<<(2 * CQ * CH + CH * CH) / 1024, 256>>>(Wq, Wk, Wv);
    k_transpose<<<dim3(SP / 64, CH / 64, BB), 256>>>(x);
    k_proj<<<dim3(8, BB, 2), 256, GEMM_SMEM>>>(bq, bk);
    k_energy<<<dim3(8, BB), 256, EN_SMEM>>>(gm);
    k_vapply<<<dim3(8, 8, BB), 256, GEMM_SMEM>>>(bv, x, out);
}